// round 9
// baseline (speedup 1.0000x reference)
#include <cuda_runtime.h>
#include <cstdint>

// ---------------------------------------------------------------------------
// Problem constants
//   feat0_c, feat1_c : [2,128,32,32] fp32
//   feat0_f, feat1_f : [2,128,64,64] fp32
// ---------------------------------------------------------------------------

static const size_t OFF_TF    = 0;
static const size_t OFF_TFC   = 2097152;
static const size_t OFF_C     = 4194304;
static const size_t OFF_CF    = 37748736;
static const size_t OFF_FLOW  = 71303168;
static const size_t OFF_FLOWF = 71319552;

// Scratch (device globals — no allocation allowed)
__device__ float g_cc[2 * 1024 * 1024];          // corr_c  [b][p0c][p1c]   8 MB
__device__ float g_i1[2 * 1024 * 4096];          // (u,v)-upsampled corr_c  33.5 MB (L2-resident)

// flow_flip column partials from softargmax stripes: [stripe(128)][b(2)][col(4096)]
__device__ float g_s_mx[128 * 2 * 4096];
__device__ float g_s_z [128 * 2 * 4096];
__device__ float g_s_sx[128 * 2 * 4096];

// ---------------------------------------------------------------------------
// helpers
// ---------------------------------------------------------------------------
__device__ __forceinline__ uint32_t pack_bf16x2(float hi, float lo) {
    uint32_t r;
    asm("cvt.rn.bf16x2.f32 %0, %1, %2;" : "=r"(r) : "f"(hi), "f"(lo));
    return r;
}

__device__ __forceinline__ void mma_bf16(float* d, const uint32_t* a, const uint32_t* b) {
    asm volatile(
        "mma.sync.aligned.m16n8k16.row.col.f32.bf16.bf16.f32 "
        "{%0,%1,%2,%3}, {%4,%5,%6,%7}, {%8,%9}, {%0,%1,%2,%3};\n"
        : "+f"(d[0]), "+f"(d[1]), "+f"(d[2]), "+f"(d[3])
        : "r"(a[0]), "r"(a[1]), "r"(a[2]), "r"(a[3]), "r"(b[0]), "r"(b[1]));
}

__device__ __forceinline__ void ldsm_x4(uint32_t* r, uint32_t saddr) {
    asm volatile("ldmatrix.sync.aligned.m8n8.x4.shared.b16 {%0,%1,%2,%3}, [%4];"
                 : "=r"(r[0]), "=r"(r[1]), "=r"(r[2]), "=r"(r[3]) : "r"(saddr));
}

__device__ __forceinline__ void lerp_weights(int i, int& i0, int& i1, float& w) {
    float f = (float)(i * 31) / 63.0f;   // align_corners scale 31/63, exact at i=0,63
    i0 = (int)f;
    w  = f - (float)i0;
    i1 = min(i0 + 1, 31);
}

__device__ __forceinline__ float warp_max(float v) {
#pragma unroll
    for (int o = 16; o; o >>= 1) v = fmaxf(v, __shfl_xor_sync(0xffffffffu, v, o));
    return v;
}
__device__ __forceinline__ float warp_sum(float v) {
#pragma unroll
    for (int o = 16; o; o >>= 1) v += __shfl_xor_sync(0xffffffffu, v, o);
    return v;
}

// ---------------------------------------------------------------------------
// Correlation GEMM (bf16x3, near-fp32 accuracy), 256 threads / 8 warps,
// 2 CTAs per SM. Block tile 128(m) x 64(n), warp tile 32x32, BK=16,
// mma.m16n8k16 + ldmatrix.x4, double-buffered smem.
// FUSE epilogue: c = 0.5*(rowinterp(g_i1) + corr), writes c + c_flip.
// ---------------------------------------------------------------------------
template <int MT, bool FUSE>
__global__ __launch_bounds__(256, 2)
void gemm_corr_kernel(const float* __restrict__ f0, const float* __restrict__ f1,
                      float* __restrict__ outC, float* __restrict__ outF)
{
    extern __shared__ uint32_t smemw[];

    const int b  = blockIdx.z;
    const int m0 = blockIdx.y * 128;
    const int n0 = blockIdx.x * 64;
    const float* A  = f0 + (size_t)b * 128 * MT;  // [K=128][MT]
    const float* Bg = f1 + (size_t)b * 128 * MT;

    const int tid  = threadIdx.x;
    const int warp = tid >> 5, lane = tid & 31;
    const int gid  = lane >> 2, tig = lane & 3;
    const int wm0  = (warp >> 1) * 32;           // 4 warp rows
    const int wn0  = (warp & 1) * 32;            // 2 warp cols

    float acc[2][4][4];
#pragma unroll
    for (int mi = 0; mi < 2; mi++)
#pragma unroll
        for (int j = 0; j < 4; j++)
#pragma unroll
            for (int r = 0; r < 4; r++) acc[mi][j][r] = 0.0f;

    // ---- producer mapping ----
    const int colA = tid & 127;
    const int kgA  = tid >> 7;                   // 0..1
    const int colB = tid & 63;
    const int kgB  = tid >> 6;                   // 0..3

    const uint32_t sbase = (uint32_t)__cvta_generic_to_shared(smemw);

    // ---- consumer ldmatrix row offsets (word units) ----
    const int Lm = lane & 7;
    const int mrowA = ((lane >> 3) & 1) * 8 + Lm;
    const int koffA = (lane >> 4) * 4;
    const uint32_t aoff0 = (uint32_t)((wm0 + mrowA) * 20 + koffA);
    const uint32_t aoff1 = (uint32_t)((wm0 + 16 + mrowA) * 20 + koffA);
    const int nrowB = Lm + ((lane >> 4) << 3);
    const int koffB = ((lane >> 3) & 1) * 4;
    const uint32_t boff0 = (uint32_t)(2560 + (wn0 + nrowB) * 20 + koffB);
    const uint32_t boff1 = (uint32_t)(2560 + (wn0 + 16 + nrowB) * 20 + koffB);

    float a0v0, a0v1, a0v2, a0v3;
    float a1v0, a1v1, a1v2, a1v3;
    float bv0, bv1, bv2, bv3;

#define LOAD_CHUNK(kb)                                                               \
    do {                                                                             \
        const float* Ar0 = A + (size_t)((kb) * 16 + kgA * 4) * MT + m0 + colA;       \
        const float* Ar1 = A + (size_t)((kb) * 16 + (kgA + 2) * 4) * MT + m0 + colA; \
        const float* Br  = Bg + (size_t)((kb) * 16 + kgB * 4) * MT + n0 + colB;      \
        a0v0 = Ar0[0]; a0v1 = Ar0[MT]; a0v2 = Ar0[2 * (size_t)MT]; a0v3 = Ar0[3 * (size_t)MT]; \
        a1v0 = Ar1[0]; a1v1 = Ar1[MT]; a1v2 = Ar1[2 * (size_t)MT]; a1v3 = Ar1[3 * (size_t)MT]; \
        bv0  = Br[0];  bv1  = Br[MT];  bv2  = Br[2 * (size_t)MT];  bv3  = Br[3 * (size_t)MT];  \
    } while (0)

#define PACK_STORE(base_w, v0, v1, v2, v3)                                           \
    do {                                                                             \
        uint32_t h0 = pack_bf16x2(v1, v0);                                           \
        uint32_t h1 = pack_bf16x2(v3, v2);                                           \
        uint32_t l0 = pack_bf16x2(v1 - __uint_as_float(h0 & 0xffff0000u),            \
                                  v0 - __uint_as_float(h0 << 16));                   \
        uint32_t l1 = pack_bf16x2(v3 - __uint_as_float(h1 & 0xffff0000u),            \
                                  v2 - __uint_as_float(h1 << 16));                   \
        *reinterpret_cast<uint2*>(&smemw[(base_w)])     = make_uint2(h0, h1);        \
        *reinterpret_cast<uint2*>(&smemw[(base_w) + 8]) = make_uint2(l0, l1);        \
    } while (0)

#define STORE_CHUNK(bufw)                                                            \
    do {                                                                             \
        PACK_STORE((bufw) + colA * 20 + 2 * kgA,       a0v0, a0v1, a0v2, a0v3);      \
        PACK_STORE((bufw) + colA * 20 + 2 * (kgA + 2), a1v0, a1v1, a1v2, a1v3);      \
        PACK_STORE((bufw) + 2560 + colB * 20 + 2 * kgB, bv0, bv1, bv2, bv3);         \
    } while (0)

    LOAD_CHUNK(0);
    STORE_CHUNK(0u);
    __syncthreads();

    for (int kb = 0; kb < 8; kb++) {
        if (kb < 7) LOAD_CHUNK(kb + 1);           // global prefetch (hidden by MMA)

        const uint32_t bw = (uint32_t)(kb & 1) * 3840u;
        uint32_t bh[2][4], bl[2][4];
        ldsm_x4(bh[0], sbase + (bw + boff0) * 4u);
        ldsm_x4(bl[0], sbase + (bw + boff0 + 8u) * 4u);
        ldsm_x4(bh[1], sbase + (bw + boff1) * 4u);
        ldsm_x4(bl[1], sbase + (bw + boff1 + 8u) * 4u);

#pragma unroll
        for (int mi = 0; mi < 2; mi++) {
            uint32_t ah[4], al[4];
            const uint32_t ao = (mi ? aoff1 : aoff0);
            ldsm_x4(ah, sbase + (bw + ao) * 4u);
            ldsm_x4(al, sbase + (bw + ao + 8u) * 4u);
#pragma unroll
            for (int j = 0; j < 4; j++) {
                const uint32_t* bfh = &bh[j >> 1][(j & 1) * 2];
                const uint32_t* bfl = &bl[j >> 1][(j & 1) * 2];
                mma_bf16(acc[mi][j], al, bfh);   // lo*hi
                mma_bf16(acc[mi][j], ah, bfl);   // hi*lo
                mma_bf16(acc[mi][j], ah, bfh);   // hi*hi
            }
        }

        if (kb < 7) STORE_CHUNK((uint32_t)((kb + 1) & 1) * 3840u);
        __syncthreads();
    }
#undef LOAD_CHUNK
#undef PACK_STORE
#undef STORE_CHUNK

    const float sc = 0.08838834764831845f;       // 1/sqrt(128)

    if constexpr (!FUSE) {
        // coarse: write scaled correlation to g_cc
        float* out = g_cc + (size_t)b * MT * MT;
        (void)outC; (void)outF;
#pragma unroll
        for (int mi = 0; mi < 2; mi++)
#pragma unroll
            for (int j = 0; j < 4; j++) {
                int r0 = m0 + wm0 + mi * 16 + gid;
                int cc = n0 + wn0 + j * 8 + 2 * tig;
                float2 v0 = make_float2(acc[mi][j][0] * sc, acc[mi][j][1] * sc);
                float2 v1 = make_float2(acc[mi][j][2] * sc, acc[mi][j][3] * sc);
                *reinterpret_cast<float2*>(&out[(size_t)r0 * MT + cc])       = v0;
                *reinterpret_cast<float2*>(&out[(size_t)(r0 + 8) * MT + cc]) = v1;
            }
    } else {
        // fine: c = 0.5*(rowinterp + corr), plus transposed write for c_flip
        float* S = reinterpret_cast<float*>(smemw);        // 128 x 65 (33.3 KB)
        float* Y = reinterpret_cast<float*>(smemw) + 8320; // 64 x 68  (17.4 KB)
        const size_t cb = (size_t)b * MT * MT;
        const int h0base = m0 >> 6;               // two h0 values: h0base, h0base+1

        // --- store corr into S (all 8 warps cover 128x64 disjointly) ---
#pragma unroll
        for (int mi = 0; mi < 2; mi++)
#pragma unroll
            for (int j = 0; j < 4; j++) {
                int r0  = wm0 + mi * 16 + gid;
                int col = wn0 + j * 8 + 2 * tig;
                S[r0 * 65 + col]           = acc[mi][j][0] * sc;
                S[r0 * 65 + col + 1]       = acc[mi][j][1] * sc;
                S[(r0 + 8) * 65 + col]     = acc[mi][j][2] * sc;
                S[(r0 + 8) * 65 + col + 1] = acc[mi][j][3] * sc;
            }

        // --- build Y: y-blend of g_i1 rows for 2 h0 values, 32 cx, 64 cols ---
#pragma unroll
        for (int t = 0; t < 4; t++) {
            int e     = tid + t * 256;            // 0..1023
            int h0loc = e >> 9;
            int cx    = (e >> 4) & 31;
            int c4    = e & 15;
            int y0, y1; float wy;
            lerp_weights(h0base + h0loc, y0, y1, wy);
            const float4* p0 = reinterpret_cast<const float4*>(
                g_i1 + ((size_t)b * 1024 + y0 * 32 + cx) * 4096 + n0) + c4;
            const float4* p1 = reinterpret_cast<const float4*>(
                g_i1 + ((size_t)b * 1024 + y1 * 32 + cx) * 4096 + n0) + c4;
            float4 a = *p0, bb = *p1;
            float4 v;
            v.x = a.x + wy * (bb.x - a.x);
            v.y = a.y + wy * (bb.y - a.y);
            v.z = a.z + wy * (bb.z - a.z);
            v.w = a.w + wy * (bb.w - a.w);
            *reinterpret_cast<float4*>(&Y[(h0loc * 32 + cx) * 68 + c4 * 4]) = v;
        }
        __syncthreads();

        // --- combine: x-blend + corr, write c, keep combined in S ---
#pragma unroll
        for (int q = 0; q < 8; q++) {
            int idx = tid + q * 256;              // float4 units over 128x64
            int r   = idx >> 4;
            int cf  = (idx & 15) << 2;
            int h0loc = r >> 6;
            int w0    = r & 63;
            int x0, x1; float wx;
            lerp_weights(w0, x0, x1, wx);
            float4 ya = *reinterpret_cast<const float4*>(&Y[(h0loc * 32 + x0) * 68 + cf]);
            float4 yb = *reinterpret_cast<const float4*>(&Y[(h0loc * 32 + x1) * 68 + cf]);
            float4 ip;
            ip.x = ya.x + wx * (yb.x - ya.x);
            ip.y = ya.y + wx * (yb.y - ya.y);
            ip.z = ya.z + wx * (yb.z - ya.z);
            ip.w = ya.w + wx * (yb.w - ya.w);
            size_t ga = cb + (size_t)(m0 + r) * MT + n0 + cf;
            float4 v;
            v.x = 0.5f * (ip.x + S[r * 65 + cf]);
            v.y = 0.5f * (ip.y + S[r * 65 + cf + 1]);
            v.z = 0.5f * (ip.z + S[r * 65 + cf + 2]);
            v.w = 0.5f * (ip.w + S[r * 65 + cf + 3]);
            *reinterpret_cast<float4*>(outC + ga) = v;
            S[r * 65 + cf]     = v.x;             // keep combined value for flip write
            S[r * 65 + cf + 1] = v.y;
            S[r * 65 + cf + 2] = v.z;
            S[r * 65 + cf + 3] = v.w;
        }
        __syncthreads();

        // --- transposed rows: c_flip[n][m0..m0+127] ---
#pragma unroll
        for (int jr = 0; jr < 8; jr++) {
            int n = warp * 8 + jr;
            size_t fb = cb + (size_t)(n0 + n) * MT + m0;
#pragma unroll
            for (int q = 0; q < 4; q++) {
                int m = lane + q * 32;            // bank = (m+n)%32 -> conflict-free
                outF[fb + m] = S[m * 65 + n];
            }
        }
    }
}

// ---------------------------------------------------------------------------
// softargmax stripe pass over c ONLY (single 134MB read):
//   grid (128, 2): stripe = 32 rows of c, b = batch. Block 256 threads.
//   Row direction (flow, t=row): full softargmax per row, written directly.
//   Column direction (flow_flip, t=col): online {max, Z, Sx} per column per
//   stripe (xn = f(row) scalar per row; yn = stripe>>1 const, applied in reduce).
// ---------------------------------------------------------------------------
__global__ __launch_bounds__(256)
void softargmax_stripe_kernel(const float* __restrict__ c, float* __restrict__ flow)
{
    const int stripe = blockIdx.x;
    const int b      = blockIdx.y;
    const int tid  = threadIdx.x;
    const int lane = tid & 31, warp = tid >> 5;
    const int r0 = stripe * 32;
    const float inv63x2 = 2.0f / 63.0f;

    // row-pass source coords for slot e: col = 4*tid + (e>>2)*1024 + (e&3)
    const float xnb = (float)((4 * tid) & 63) * inv63x2 - 1.0f;   // + (e&3)*inv
    const float ynb = (float)(tid >> 4) * inv63x2 - 1.0f;         // + (e>>2)*16*inv

    float cmx[16], cz[16], csx[16];
#pragma unroll
    for (int e = 0; e < 16; e++) { cmx[e] = -1e30f; cz[e] = 0.0f; csx[e] = 0.0f; }

    __shared__ float sm[8], szs[8], ssx[8], ssy[8];

    for (int rr = 0; rr < 32; rr++) {
        const int s_row = r0 + rr;
        const float* row = c + ((size_t)b * 4096 + s_row) * 4096;
        float v[16];
#pragma unroll
        for (int q = 0; q < 4; q++) {
            float4 x = reinterpret_cast<const float4*>(row)[tid + q * 256];
            v[q * 4] = x.x; v[q * 4 + 1] = x.y; v[q * 4 + 2] = x.z; v[q * 4 + 3] = x.w;
        }

        // --- column online update (flow_flip partials); xn scalar per row ---
        const float xnr = (float)(s_row & 63) * inv63x2 - 1.0f;
#pragma unroll
        for (int e = 0; e < 16; e++) {
            float vv = v[e];
            if (vv > cmx[e]) {
                float s = __expf((cmx[e] - vv) * 50.0f);
                cz[e]  = cz[e]  * s + 1.0f;
                csx[e] = csx[e] * s + xnr;
                cmx[e] = vv;
            } else {
                float d = (vv - cmx[e]) * 50.0f;
                if (d > -25.0f) { float ee = __expf(d); cz[e] += ee; csx[e] += ee * xnr; }
            }
        }

        // --- row softargmax (flow row t = s_row) ---
        float mx = v[0];
#pragma unroll
        for (int e = 1; e < 16; e++) mx = fmaxf(mx, v[e]);
        mx = warp_max(mx);
        if (lane == 0) sm[warp] = mx;
        __syncthreads();
        mx = sm[0];
#pragma unroll
        for (int i = 1; i < 8; i++) mx = fmaxf(mx, sm[i]);

        float Z = 0.0f, Sx = 0.0f, Sy = 0.0f;
#pragma unroll
        for (int e = 0; e < 16; e++) {
            float d = (v[e] - mx) * 50.0f;
            if (d > -25.0f) {
                float ee = __expf(d);
                Z  += ee;
                Sx += ee * (xnb + (float)(e & 3) * inv63x2);
                Sy += ee * (ynb + (float)((e >> 2) * 16) * inv63x2);
            }
        }
        Z = warp_sum(Z); Sx = warp_sum(Sx); Sy = warp_sum(Sy);
        if (lane == 0) { szs[warp] = Z; ssx[warp] = Sx; ssy[warp] = Sy; }
        __syncthreads();
        if (tid == 0) {
            float z = 0.0f, X = 0.0f, Yv = 0.0f;
#pragma unroll
            for (int i = 0; i < 8; i++) { z += szs[i]; X += ssx[i]; Yv += ssy[i]; }
            float gx = X / z, gy = Yv / z;
            float w = (float)(s_row & 63), h = (float)(s_row >> 6);
            flow[(size_t)b * 8192 + s_row]        = (gx + 1.0f) * 31.5f - w;
            flow[(size_t)b * 8192 + 4096 + s_row] = (gy + 1.0f) * 31.5f - h;
        }
    }

    // write column partials (coalesced float4)
    const size_t pb = ((size_t)stripe * 2 + b) * 4096;
#pragma unroll
    for (int q = 0; q < 4; q++) {
        int col = 4 * tid + q * 1024;
        *reinterpret_cast<float4*>(&g_s_mx[pb + col]) =
            make_float4(cmx[q*4], cmx[q*4+1], cmx[q*4+2], cmx[q*4+3]);
        *reinterpret_cast<float4*>(&g_s_z [pb + col]) =
            make_float4(cz[q*4], cz[q*4+1], cz[q*4+2], cz[q*4+3]);
        *reinterpret_cast<float4*>(&g_s_sx[pb + col]) =
            make_float4(csx[q*4], csx[q*4+1], csx[q*4+2], csx[q*4+3]);
    }
}

// ---------------------------------------------------------------------------
// flow_flip reduce: merge 128 stripe partials per (b, col)
// grid (16, 2) x 256: t = col, b = batch
// ---------------------------------------------------------------------------
__global__ __launch_bounds__(256)
void flow_flip_reduce_kernel(float* __restrict__ flf)
{
    const int t = blockIdx.x * 256 + threadIdx.x;
    const int b = blockIdx.y;
    const float inv63x2 = 2.0f / 63.0f;

    float M = -1e30f, Z = 0.0f, Sx = 0.0f, Sy = 0.0f;
    for (int j = 0; j < 128; j++) {
        size_t idx = ((size_t)j * 2 + b) * 4096 + t;
        float mj = g_s_mx[idx], zj = g_s_z[idx], sxj = g_s_sx[idx];
        float yn = (float)(j >> 1) * inv63x2 - 1.0f;     // rows j*32..j*32+31 share h0=j>>1
        if (mj > M) {
            float s = __expf((M - mj) * 50.0f);
            Z *= s; Sx *= s; Sy *= s; M = mj;
        }
        float w = __expf((mj - M) * 50.0f);
        Z += w * zj; Sx += w * sxj; Sy += w * yn * zj;
    }
    float gx = Sx / Z, gy = Sy / Z;
    float w = (float)(t & 63), h = (float)(t >> 6);
    flf[(size_t)b * 8192 + t]        = (gx + 1.0f) * 31.5f - w;
    flf[(size_t)b * 8192 + 4096 + t] = (gy + 1.0f) * 31.5f - h;
}

// ---------------------------------------------------------------------------
// trans_features_coarse: bilinear 32->64 (align_corners) per channel
// ---------------------------------------------------------------------------
__global__ __launch_bounds__(256)
void resize_coarse_kernel(const float* __restrict__ a, const float* __restrict__ bsrc,
                          float* __restrict__ out)
{
    __shared__ float s[1024];
    int blk = blockIdx.x;                        // 0..511
    int bb = blk >> 8, ii = (blk >> 7) & 1, ch = blk & 127;
    const float* in = (ii ? bsrc : a) + ((size_t)bb * 128 + ch) * 1024;
    float* o = out + (((size_t)bb * 2 + ii) * 128 + ch) * 4096;
    int tid = threadIdx.x;
#pragma unroll
    for (int q = 0; q < 4; q++) s[tid + q * 256] = in[tid + q * 256];
    __syncthreads();
#pragma unroll
    for (int q = 0; q < 16; q++) {
        int oi = tid + q * 256;
        int oy = oi >> 6, ox = oi & 63;
        int y0, y1, x0, x1; float wy, wx;
        lerp_weights(oy, y0, y1, wy);
        lerp_weights(ox, x0, x1, wx);
        float v = (1.0f - wy) * ((1.0f - wx) * s[y0 * 32 + x0] + wx * s[y0 * 32 + x1])
                +         wy  * ((1.0f - wx) * s[y1 * 32 + x0] + wx * s[y1 * 32 + x1]);
        o[oi] = v;
    }
}

// ---------------------------------------------------------------------------
// interp pass A: per (b,p0c) row, upsample (u,v) 32x32 -> 64x64
// ---------------------------------------------------------------------------
__global__ __launch_bounds__(256)
void interpA_kernel()
{
    __shared__ float s[1024];
    int blk = blockIdx.x;                        // 0..2047 = b*1024 + p0c
    const float* in = g_cc + (size_t)blk * 1024;
    float* o = g_i1 + (size_t)blk * 4096;
    int tid = threadIdx.x;
#pragma unroll
    for (int q = 0; q < 4; q++) s[tid + q * 256] = in[tid + q * 256];
    __syncthreads();
#pragma unroll
    for (int q = 0; q < 16; q++) {
        int oi = tid + q * 256;
        int oy = oi >> 6, ox = oi & 63;
        int y0, y1, x0, x1; float wy, wx;
        lerp_weights(oy, y0, y1, wy);
        lerp_weights(ox, x0, x1, wx);
        float v = (1.0f - wy) * ((1.0f - wx) * s[y0 * 32 + x0] + wx * s[y0 * 32 + x1])
                +         wy  * ((1.0f - wx) * s[y1 * 32 + x0] + wx * s[y1 * 32 + x1]);
        o[oi] = v;
    }
}

// ---------------------------------------------------------------------------
// launch
// ---------------------------------------------------------------------------
extern "C" void kernel_launch(void* const* d_in, const int* in_sizes, int n_in,
                              void* d_out, int out_size)
{
    (void)in_sizes; (void)n_in; (void)out_size;
    const float* f0c = (const float*)d_in[0];
    const float* f1c = (const float*)d_in[1];
    const float* f0f = (const float*)d_in[2];
    const float* f1f = (const float*)d_in[3];
    float* out = (float*)d_out;

    cudaFuncSetAttribute(gemm_corr_kernel<4096, true>,
                         cudaFuncAttributeMaxDynamicSharedMemorySize, 50688);

    // trans_features = stack([feat0_f, feat1_f], axis=1)
    const size_t chunk = (size_t)128 * 4096;
    cudaMemcpyAsync(out + OFF_TF + 0 * chunk, f0f,         chunk * 4, cudaMemcpyDeviceToDevice, 0);
    cudaMemcpyAsync(out + OFF_TF + 1 * chunk, f1f,         chunk * 4, cudaMemcpyDeviceToDevice, 0);
    cudaMemcpyAsync(out + OFF_TF + 2 * chunk, f0f + chunk, chunk * 4, cudaMemcpyDeviceToDevice, 0);
    cudaMemcpyAsync(out + OFF_TF + 3 * chunk, f1f + chunk, chunk * 4, cudaMemcpyDeviceToDevice, 0);

    resize_coarse_kernel<<<512, 256>>>(f0c, f1c, out + OFF_TFC);

    gemm_corr_kernel<1024, false><<<dim3(16, 8, 2), 256, 30720>>>(f0c, f1c, nullptr, nullptr);
    interpA_kernel<<<2048, 256>>>();
    gemm_corr_kernel<4096, true><<<dim3(64, 32, 2), 256, 50688>>>(f0f, f1f, out + OFF_C, out + OFF_CF);

    softargmax_stripe_kernel<<<dim3(128, 2), 256>>>(out + OFF_C, out + OFF_FLOW);
    flow_flip_reduce_kernel<<<dim3(16, 2), 256>>>(out + OFF_FLOWF);
}

// round 10
// speedup vs baseline: 1.2547x; 1.2547x over previous
#include <cuda_runtime.h>
#include <cstdint>

// ---------------------------------------------------------------------------
// Problem constants
//   feat0_c, feat1_c : [2,128,32,32] fp32
//   feat0_f, feat1_f : [2,128,64,64] fp32
// ---------------------------------------------------------------------------

static const size_t OFF_TF    = 0;
static const size_t OFF_TFC   = 2097152;
static const size_t OFF_C     = 4194304;
static const size_t OFF_CF    = 37748736;
static const size_t OFF_FLOW  = 71303168;
static const size_t OFF_FLOWF = 71319552;

// Scratch (device globals — no allocation allowed)
__device__ float g_cc[2 * 1024 * 1024];          // corr_c  [b][p0c][p1c]   8 MB
__device__ float g_i1[2 * 1024 * 4096];          // (u,v)-upsampled corr_c  33.5 MB (L2-resident)

// ---------------------------------------------------------------------------
// helpers
// ---------------------------------------------------------------------------
__device__ __forceinline__ uint32_t pack_bf16x2(float hi, float lo) {
    uint32_t r;
    asm("cvt.rn.bf16x2.f32 %0, %1, %2;" : "=r"(r) : "f"(hi), "f"(lo));
    return r;
}

__device__ __forceinline__ void mma_bf16(float* d, const uint32_t* a, const uint32_t* b) {
    asm volatile(
        "mma.sync.aligned.m16n8k16.row.col.f32.bf16.bf16.f32 "
        "{%0,%1,%2,%3}, {%4,%5,%6,%7}, {%8,%9}, {%0,%1,%2,%3};\n"
        : "+f"(d[0]), "+f"(d[1]), "+f"(d[2]), "+f"(d[3])
        : "r"(a[0]), "r"(a[1]), "r"(a[2]), "r"(a[3]), "r"(b[0]), "r"(b[1]));
}

__device__ __forceinline__ void ldsm_x4(uint32_t* r, uint32_t saddr) {
    asm volatile("ldmatrix.sync.aligned.m8n8.x4.shared.b16 {%0,%1,%2,%3}, [%4];"
                 : "=r"(r[0]), "=r"(r[1]), "=r"(r[2]), "=r"(r[3]) : "r"(saddr));
}

__device__ __forceinline__ void lerp_weights(int i, int& i0, int& i1, float& w) {
    float f = (float)(i * 31) / 63.0f;   // align_corners scale 31/63, exact at i=0,63
    i0 = (int)f;
    w  = f - (float)i0;
    i1 = min(i0 + 1, 31);
}

// ---------------------------------------------------------------------------
// Correlation GEMM (bf16x3, near-fp32 accuracy), 256 threads / 8 warps,
// 2 CTAs per SM. Block tile 128(m) x 64(n), warp tile 32x32, BK=16,
// mma.m16n8k16 + ldmatrix.x4, double-buffered smem.
// FUSE epilogue: c = 0.5*(rowinterp(g_i1) + corr), writes c + c_flip.
// ---------------------------------------------------------------------------
template <int MT, bool FUSE>
__global__ __launch_bounds__(256, 2)
void gemm_corr_kernel(const float* __restrict__ f0, const float* __restrict__ f1,
                      float* __restrict__ outC, float* __restrict__ outF)
{
    extern __shared__ uint32_t smemw[];

    const int b  = blockIdx.z;
    const int m0 = blockIdx.y * 128;
    const int n0 = blockIdx.x * 64;
    const float* A  = f0 + (size_t)b * 128 * MT;  // [K=128][MT]
    const float* Bg = f1 + (size_t)b * 128 * MT;

    const int tid  = threadIdx.x;
    const int warp = tid >> 5, lane = tid & 31;
    const int gid  = lane >> 2, tig = lane & 3;
    const int wm0  = (warp >> 1) * 32;           // 4 warp rows
    const int wn0  = (warp & 1) * 32;            // 2 warp cols

    float acc[2][4][4];
#pragma unroll
    for (int mi = 0; mi < 2; mi++)
#pragma unroll
        for (int j = 0; j < 4; j++)
#pragma unroll
            for (int r = 0; r < 4; r++) acc[mi][j][r] = 0.0f;

    // ---- producer mapping ----
    const int colA = tid & 127;
    const int kgA  = tid >> 7;                   // 0..1
    const int colB = tid & 63;
    const int kgB  = tid >> 6;                   // 0..3

    const uint32_t sbase = (uint32_t)__cvta_generic_to_shared(smemw);

    // ---- consumer ldmatrix row offsets (word units) ----
    const int Lm = lane & 7;
    const int mrowA = ((lane >> 3) & 1) * 8 + Lm;
    const int koffA = (lane >> 4) * 4;
    const uint32_t aoff0 = (uint32_t)((wm0 + mrowA) * 20 + koffA);
    const uint32_t aoff1 = (uint32_t)((wm0 + 16 + mrowA) * 20 + koffA);
    const int nrowB = Lm + ((lane >> 4) << 3);
    const int koffB = ((lane >> 3) & 1) * 4;
    const uint32_t boff0 = (uint32_t)(2560 + (wn0 + nrowB) * 20 + koffB);
    const uint32_t boff1 = (uint32_t)(2560 + (wn0 + 16 + nrowB) * 20 + koffB);

    float a0v0, a0v1, a0v2, a0v3;
    float a1v0, a1v1, a1v2, a1v3;
    float bv0, bv1, bv2, bv3;

#define LOAD_CHUNK(kb)                                                               \
    do {                                                                             \
        const float* Ar0 = A + (size_t)((kb) * 16 + kgA * 4) * MT + m0 + colA;       \
        const float* Ar1 = A + (size_t)((kb) * 16 + (kgA + 2) * 4) * MT + m0 + colA; \
        const float* Br  = Bg + (size_t)((kb) * 16 + kgB * 4) * MT + n0 + colB;      \
        a0v0 = Ar0[0]; a0v1 = Ar0[MT]; a0v2 = Ar0[2 * (size_t)MT]; a0v3 = Ar0[3 * (size_t)MT]; \
        a1v0 = Ar1[0]; a1v1 = Ar1[MT]; a1v2 = Ar1[2 * (size_t)MT]; a1v3 = Ar1[3 * (size_t)MT]; \
        bv0  = Br[0];  bv1  = Br[MT];  bv2  = Br[2 * (size_t)MT];  bv3  = Br[3 * (size_t)MT];  \
    } while (0)

#define PACK_STORE(base_w, v0, v1, v2, v3)                                           \
    do {                                                                             \
        uint32_t h0 = pack_bf16x2(v1, v0);                                           \
        uint32_t h1 = pack_bf16x2(v3, v2);                                           \
        uint32_t l0 = pack_bf16x2(v1 - __uint_as_float(h0 & 0xffff0000u),            \
                                  v0 - __uint_as_float(h0 << 16));                   \
        uint32_t l1 = pack_bf16x2(v3 - __uint_as_float(h1 & 0xffff0000u),            \
                                  v2 - __uint_as_float(h1 << 16));                   \
        *reinterpret_cast<uint2*>(&smemw[(base_w)])     = make_uint2(h0, h1);        \
        *reinterpret_cast<uint2*>(&smemw[(base_w) + 8]) = make_uint2(l0, l1);        \
    } while (0)

#define STORE_CHUNK(bufw)                                                            \
    do {                                                                             \
        PACK_STORE((bufw) + colA * 20 + 2 * kgA,       a0v0, a0v1, a0v2, a0v3);      \
        PACK_STORE((bufw) + colA * 20 + 2 * (kgA + 2), a1v0, a1v1, a1v2, a1v3);      \
        PACK_STORE((bufw) + 2560 + colB * 20 + 2 * kgB, bv0, bv1, bv2, bv3);         \
    } while (0)

    LOAD_CHUNK(0);
    STORE_CHUNK(0u);
    __syncthreads();

    for (int kb = 0; kb < 8; kb++) {
        if (kb < 7) LOAD_CHUNK(kb + 1);           // global prefetch (hidden by MMA)

        const uint32_t bw = (uint32_t)(kb & 1) * 3840u;
        uint32_t bh[2][4], bl[2][4];
        ldsm_x4(bh[0], sbase + (bw + boff0) * 4u);
        ldsm_x4(bl[0], sbase + (bw + boff0 + 8u) * 4u);
        ldsm_x4(bh[1], sbase + (bw + boff1) * 4u);
        ldsm_x4(bl[1], sbase + (bw + boff1 + 8u) * 4u);

#pragma unroll
        for (int mi = 0; mi < 2; mi++) {
            uint32_t ah[4], al[4];
            const uint32_t ao = (mi ? aoff1 : aoff0);
            ldsm_x4(ah, sbase + (bw + ao) * 4u);
            ldsm_x4(al, sbase + (bw + ao + 8u) * 4u);
#pragma unroll
            for (int j = 0; j < 4; j++) {
                const uint32_t* bfh = &bh[j >> 1][(j & 1) * 2];
                const uint32_t* bfl = &bl[j >> 1][(j & 1) * 2];
                mma_bf16(acc[mi][j], al, bfh);   // lo*hi
                mma_bf16(acc[mi][j], ah, bfl);   // hi*lo
                mma_bf16(acc[mi][j], ah, bfh);   // hi*hi
            }
        }

        if (kb < 7) STORE_CHUNK((uint32_t)((kb + 1) & 1) * 3840u);
        __syncthreads();
    }
#undef LOAD_CHUNK
#undef PACK_STORE
#undef STORE_CHUNK

    const float sc = 0.08838834764831845f;       // 1/sqrt(128)

    if constexpr (!FUSE) {
        // coarse: write scaled correlation to g_cc
        float* out = g_cc + (size_t)b * MT * MT;
        (void)outC; (void)outF;
#pragma unroll
        for (int mi = 0; mi < 2; mi++)
#pragma unroll
            for (int j = 0; j < 4; j++) {
                int r0 = m0 + wm0 + mi * 16 + gid;
                int cc = n0 + wn0 + j * 8 + 2 * tig;
                float2 v0 = make_float2(acc[mi][j][0] * sc, acc[mi][j][1] * sc);
                float2 v1 = make_float2(acc[mi][j][2] * sc, acc[mi][j][3] * sc);
                *reinterpret_cast<float2*>(&out[(size_t)r0 * MT + cc])       = v0;
                *reinterpret_cast<float2*>(&out[(size_t)(r0 + 8) * MT + cc]) = v1;
            }
    } else {
        // fine: c = 0.5*(rowinterp + corr), plus transposed write for c_flip
        float* S = reinterpret_cast<float*>(smemw);        // 128 x 65 (33.3 KB)
        float* Y = reinterpret_cast<float*>(smemw) + 8320; // 64 x 68  (17.4 KB)
        const size_t cb = (size_t)b * MT * MT;
        const int h0base = m0 >> 6;               // two h0 values: h0base, h0base+1

        // --- store corr into S (all 8 warps cover 128x64 disjointly) ---
#pragma unroll
        for (int mi = 0; mi < 2; mi++)
#pragma unroll
            for (int j = 0; j < 4; j++) {
                int r0  = wm0 + mi * 16 + gid;
                int col = wn0 + j * 8 + 2 * tig;
                S[r0 * 65 + col]           = acc[mi][j][0] * sc;
                S[r0 * 65 + col + 1]       = acc[mi][j][1] * sc;
                S[(r0 + 8) * 65 + col]     = acc[mi][j][2] * sc;
                S[(r0 + 8) * 65 + col + 1] = acc[mi][j][3] * sc;
            }

        // --- build Y: y-blend of g_i1 rows for 2 h0 values, 32 cx, 64 cols ---
#pragma unroll
        for (int t = 0; t < 4; t++) {
            int e     = tid + t * 256;            // 0..1023
            int h0loc = e >> 9;
            int cx    = (e >> 4) & 31;
            int c4    = e & 15;
            int y0, y1; float wy;
            lerp_weights(h0base + h0loc, y0, y1, wy);
            const float4* p0 = reinterpret_cast<const float4*>(
                g_i1 + ((size_t)b * 1024 + y0 * 32 + cx) * 4096 + n0) + c4;
            const float4* p1 = reinterpret_cast<const float4*>(
                g_i1 + ((size_t)b * 1024 + y1 * 32 + cx) * 4096 + n0) + c4;
            float4 a = *p0, bb = *p1;
            float4 v;
            v.x = a.x + wy * (bb.x - a.x);
            v.y = a.y + wy * (bb.y - a.y);
            v.z = a.z + wy * (bb.z - a.z);
            v.w = a.w + wy * (bb.w - a.w);
            *reinterpret_cast<float4*>(&Y[(h0loc * 32 + cx) * 68 + c4 * 4]) = v;
        }
        __syncthreads();

        // --- combine: x-blend + corr, write c, keep combined in S ---
#pragma unroll
        for (int q = 0; q < 8; q++) {
            int idx = tid + q * 256;              // float4 units over 128x64
            int r   = idx >> 4;
            int cf  = (idx & 15) << 2;
            int h0loc = r >> 6;
            int w0    = r & 63;
            int x0, x1; float wx;
            lerp_weights(w0, x0, x1, wx);
            float4 ya = *reinterpret_cast<const float4*>(&Y[(h0loc * 32 + x0) * 68 + cf]);
            float4 yb = *reinterpret_cast<const float4*>(&Y[(h0loc * 32 + x1) * 68 + cf]);
            float4 ip;
            ip.x = ya.x + wx * (yb.x - ya.x);
            ip.y = ya.y + wx * (yb.y - ya.y);
            ip.z = ya.z + wx * (yb.z - ya.z);
            ip.w = ya.w + wx * (yb.w - ya.w);
            size_t ga = cb + (size_t)(m0 + r) * MT + n0 + cf;
            float4 v;
            v.x = 0.5f * (ip.x + S[r * 65 + cf]);
            v.y = 0.5f * (ip.y + S[r * 65 + cf + 1]);
            v.z = 0.5f * (ip.z + S[r * 65 + cf + 2]);
            v.w = 0.5f * (ip.w + S[r * 65 + cf + 3]);
            *reinterpret_cast<float4*>(outC + ga) = v;
            S[r * 65 + cf]     = v.x;             // keep combined value for flip write
            S[r * 65 + cf + 1] = v.y;
            S[r * 65 + cf + 2] = v.z;
            S[r * 65 + cf + 3] = v.w;
        }
        __syncthreads();

        // --- transposed rows: c_flip[n][m0..m0+127] ---
#pragma unroll
        for (int jr = 0; jr < 8; jr++) {
            int n = warp * 8 + jr;
            size_t fb = cb + (size_t)(n0 + n) * MT + m0;
#pragma unroll
            for (int q = 0; q < 4; q++) {
                int m = lane + q * 32;            // bank = (m+n)%32 -> conflict-free
                outF[fb + m] = S[m * 65 + n];
            }
        }
    }
}

// ---------------------------------------------------------------------------
// trans_features_coarse: bilinear 32->64 (align_corners) per channel
// ---------------------------------------------------------------------------
__global__ __launch_bounds__(256)
void resize_coarse_kernel(const float* __restrict__ a, const float* __restrict__ bsrc,
                          float* __restrict__ out)
{
    __shared__ float s[1024];
    int blk = blockIdx.x;                        // 0..511
    int bb = blk >> 8, ii = (blk >> 7) & 1, ch = blk & 127;
    const float* in = (ii ? bsrc : a) + ((size_t)bb * 128 + ch) * 1024;
    float* o = out + (((size_t)bb * 2 + ii) * 128 + ch) * 4096;
    int tid = threadIdx.x;
#pragma unroll
    for (int q = 0; q < 4; q++) s[tid + q * 256] = in[tid + q * 256];
    __syncthreads();
#pragma unroll
    for (int q = 0; q < 16; q++) {
        int oi = tid + q * 256;
        int oy = oi >> 6, ox = oi & 63;
        int y0, y1, x0, x1; float wy, wx;
        lerp_weights(oy, y0, y1, wy);
        lerp_weights(ox, x0, x1, wx);
        float v = (1.0f - wy) * ((1.0f - wx) * s[y0 * 32 + x0] + wx * s[y0 * 32 + x1])
                +         wy  * ((1.0f - wx) * s[y1 * 32 + x0] + wx * s[y1 * 32 + x1]);
        o[oi] = v;
    }
}

// ---------------------------------------------------------------------------
// interp pass A: per (b,p0c) row, upsample (u,v) 32x32 -> 64x64
// ---------------------------------------------------------------------------
__global__ __launch_bounds__(256)
void interpA_kernel()
{
    __shared__ float s[1024];
    int blk = blockIdx.x;                        // 0..2047 = b*1024 + p0c
    const float* in = g_cc + (size_t)blk * 1024;
    float* o = g_i1 + (size_t)blk * 4096;
    int tid = threadIdx.x;
#pragma unroll
    for (int q = 0; q < 4; q++) s[tid + q * 256] = in[tid + q * 256];
    __syncthreads();
#pragma unroll
    for (int q = 0; q < 16; q++) {
        int oi = tid + q * 256;
        int oy = oi >> 6, ox = oi & 63;
        int y0, y1, x0, x1; float wy, wx;
        lerp_weights(oy, y0, y1, wy);
        lerp_weights(ox, x0, x1, wx);
        float v = (1.0f - wy) * ((1.0f - wx) * s[y0 * 32 + x0] + wx * s[y0 * 32 + x1])
                +         wy  * ((1.0f - wx) * s[y1 * 32 + x0] + wx * s[y1 * 32 + x1]);
        o[oi] = v;
    }
}

// ---------------------------------------------------------------------------
// soft-argmax: softmax(row/0.02) over 4096 source positions, marginal means.
// One block per (target pixel, batch); z selects (c -> flow) / (c_flip -> flow_flip).
// L2-locality: the fine GEMM finishes with batch b=1's c/c_flip (~134MB ~= L2)
// resident, so iterate b=1 first and rows descending to harvest L2 hits.
// ---------------------------------------------------------------------------
__global__ __launch_bounds__(256)
void softargmax_kernel(const float* __restrict__ c0, const float* __restrict__ c1,
                       float* __restrict__ fl0, float* __restrict__ fl1)
{
    const int t  = 4095 - blockIdx.x;            // descending rows (GEMM tail first)
    const int bb = 1 - blockIdx.y;               // batch 1 first (still L2-resident)
    const float* cmat = blockIdx.z ? c1 : c0;
    float* flow       = blockIdx.z ? fl1 : fl0;
    const float* row = cmat + ((size_t)bb * 4096 + t) * 4096;
    const int tid = threadIdx.x;
    const int warp = tid >> 5, lane = tid & 31;

    float v[16];
    const float4* r4 = reinterpret_cast<const float4*>(row) + tid * 4;
#pragma unroll
    for (int q = 0; q < 4; q++) {
        float4 x = r4[q];
        v[q * 4] = x.x; v[q * 4 + 1] = x.y; v[q * 4 + 2] = x.z; v[q * 4 + 3] = x.w;
    }

    float mx = v[0];
#pragma unroll
    for (int e = 1; e < 16; e++) mx = fmaxf(mx, v[e]);
#pragma unroll
    for (int o = 16; o; o >>= 1) mx = fmaxf(mx, __shfl_xor_sync(0xffffffffu, mx, o));

    __shared__ float smax[8];
    if (lane == 0) smax[warp] = mx;
    __syncthreads();
    mx = smax[0];
#pragma unroll
    for (int i = 1; i < 8; i++) mx = fmaxf(mx, smax[i]);

    float Z = 0.0f, Sx = 0.0f, Sy = 0.0f;
    const int base = tid * 16;
#pragma unroll
    for (int e = 0; e < 16; e++) {
        float tt = (v[e] - mx) * 50.0f;           // /beta = *50
        if (tt > -25.0f) {                        // skipped terms < 1.4e-11 * Z
            float ee = __expf(tt);
            int idx = base + e;
            float xn = (float)((idx & 63) * 2) / 63.0f - 1.0f;
            float yn = (float)((idx >> 6) * 2) / 63.0f - 1.0f;
            Z += ee; Sx += ee * xn; Sy += ee * yn;
        }
    }
#pragma unroll
    for (int o = 16; o; o >>= 1) {
        Z  += __shfl_xor_sync(0xffffffffu, Z,  o);
        Sx += __shfl_xor_sync(0xffffffffu, Sx, o);
        Sy += __shfl_xor_sync(0xffffffffu, Sy, o);
    }
    __shared__ float sz[8], sxs[8], sys[8];
    if (lane == 0) { sz[warp] = Z; sxs[warp] = Sx; sys[warp] = Sy; }
    __syncthreads();
    if (tid == 0) {
        float z = 0.0f, X = 0.0f, Y = 0.0f;
#pragma unroll
        for (int i = 0; i < 8; i++) { z += sz[i]; X += sxs[i]; Y += sys[i]; }
        float gx = X / z, gy = Y / z;
        float w = (float)(t & 63), h = (float)(t >> 6);
        flow[(size_t)bb * 2 * 4096 + t]        = (gx + 1.0f) * 31.5f - w;
        flow[(size_t)bb * 2 * 4096 + 4096 + t] = (gy + 1.0f) * 31.5f - h;
    }
}

// ---------------------------------------------------------------------------
// launch
// ---------------------------------------------------------------------------
extern "C" void kernel_launch(void* const* d_in, const int* in_sizes, int n_in,
                              void* d_out, int out_size)
{
    (void)in_sizes; (void)n_in; (void)out_size;
    const float* f0c = (const float*)d_in[0];
    const float* f1c = (const float*)d_in[1];
    const float* f0f = (const float*)d_in[2];
    const float* f1f = (const float*)d_in[3];
    float* out = (float*)d_out;

    cudaFuncSetAttribute(gemm_corr_kernel<4096, true>,
                         cudaFuncAttributeMaxDynamicSharedMemorySize, 50688);

    // trans_features = stack([feat0_f, feat1_f], axis=1)
    const size_t chunk = (size_t)128 * 4096;
    cudaMemcpyAsync(out + OFF_TF + 0 * chunk, f0f,         chunk * 4, cudaMemcpyDeviceToDevice, 0);
    cudaMemcpyAsync(out + OFF_TF + 1 * chunk, f1f,         chunk * 4, cudaMemcpyDeviceToDevice, 0);
    cudaMemcpyAsync(out + OFF_TF + 2 * chunk, f0f + chunk, chunk * 4, cudaMemcpyDeviceToDevice, 0);
    cudaMemcpyAsync(out + OFF_TF + 3 * chunk, f1f + chunk, chunk * 4, cudaMemcpyDeviceToDevice, 0);

    resize_coarse_kernel<<<512, 256>>>(f0c, f1c, out + OFF_TFC);

    gemm_corr_kernel<1024, false><<<dim3(16, 8, 2), 256, 30720>>>(f0c, f1c, nullptr, nullptr);
    interpA_kernel<<<2048, 256>>>();
    gemm_corr_kernel<4096, true><<<dim3(64, 32, 2), 256, 50688>>>(f0f, f1f, out + OFF_C, out + OFF_CF);

    softargmax_kernel<<<dim3(4096, 2, 2), 256>>>(out + OFF_C, out + OFF_CF,
                                                 out + OFF_FLOW, out + OFF_FLOWF);
}